// round 15
// baseline (speedup 1.0000x reference)
#include <cuda_runtime.h>

#define IMG     512
#define TX      32
#define TY      32
#define RAD     5
#define HTILE   (TY + 10)   /* 42 */
#define WTILE   (TX + 10)   /* 42 */
#define WPAD    46   /* float2 row stride: 368B = odd x16 mod 128 -> conflict-free */
#define HPAD4   33   /* float4 row stride: 528B = odd x16 mod 128 -> conflict-free */
#define GX      (IMG / TX)  /* 16 */
#define GY      (IMG / TY)  /* 16 */
#define NPLANES 48
#define NBLK    (GX * GY * NPLANES)  /* 12288 */
#define NPIXD   12582912.0

// Gaussian window (sigma=1.5, K=11), normalized.
#define G0  1.0283800e-03f
#define G1  7.5988187e-03f
#define G2  3.6000773e-02f
#define G3  1.0936069e-01f
#define G4  2.1300553e-01f
#define G5  2.6601131e-01f

typedef unsigned long long u64;

// Packed f32x2 helpers (Blackwell). One FFMA2 = two independent fp32 FMAs.
__device__ __forceinline__ u64 pack2(float lo, float hi) {
    u64 r;
    asm("mov.b64 %0, {%1, %2};" : "=l"(r) : "f"(lo), "f"(hi));
    return r;
}
__device__ __forceinline__ void unpack2(u64 v, float& lo, float& hi) {
    asm("mov.b64 {%0, %1}, %2;" : "=f"(lo), "=f"(hi) : "l"(v));
}
#define FMA2(acc, coef, v) \
    asm("fma.rn.f32x2 %0, %1, %2, %0;" : "+l"(acc) : "l"(coef), "l"(v))

// Packed coefficient pair for tap k (symmetric window), compile-time select.
#define GWP(k) ((k)==0||(k)==10 ? GP0 : (k)==1||(k)==9 ? GP1 : \
                (k)==2||(k)==8  ? GP2 : (k)==3||(k)==7 ? GP3 : \
                (k)==4||(k)==6  ? GP4 : GP5)

__device__ float g_part[NBLK];
__device__ int   g_count = 0;

__global__ __launch_bounds__(256, 6) void ssim_main(const float* __restrict__ x,
                                                    const float* __restrict__ y,
                                                    float* __restrict__ out) {
    // After horizontal conv, all 4 fields packed per point: (hx, hy, hz, hw)
    //   z = x^2 + y^2 (conv linearity),  w = x*y
    __shared__ float2 xys[HTILE][WPAD];     // (x, y) input tile   15.5 KB
    __shared__ float4 Hs[HTILE][HPAD4];     // packed H fields     22.2 KB
    __shared__ float  red[4];

    const int tid   = threadIdx.x;
    const int plane = blockIdx.z;
    const int c0    = blockIdx.x * TX;
    const int r0    = blockIdx.y * TY;
    const float* xp = x + (size_t)plane * (IMG * IMG);
    const float* yp = y + (size_t)plane * (IMG * IMG);

    // Packed (G,G) coefficient pairs — warp-uniform.
    const u64 GP0 = pack2(G0, G0);
    const u64 GP1 = pack2(G1, G1);
    const u64 GP2 = pack2(G2, G2);
    const u64 GP3 = pack2(G3, G3);
    const u64 GP4 = pack2(G4, G4);
    const u64 GP5 = pack2(G5, G5);

    // ---- Phase 0: halo load, one column per thread, 7 rows unrolled ----
    if (tid < 252) {
        const int c  = tid % WTILE;       // tile column 0..41
        const int g6 = tid / WTILE;       // row group 0..5
        const int gc = c0 + c - RAD;
        const bool okc = (gc >= 0) & (gc < IMG);
#pragma unroll
        for (int k = 0; k < 7; k++) {
            int lr = g6 * 7 + k;
            int gr = r0 + lr - RAD;
            bool ok = okc & (gr >= 0) & (gr < IMG);
            float xv = 0.f, yv = 0.f;
            if (ok) {
                int g = gr * IMG + gc;
                xv = xp[g];
                yv = yp[g];
            }
            xys[lr][c] = make_float2(xv, yv);
        }
    }
    __syncthreads();

    // ---- Phase 1: horizontal conv; lanes span ROWS (conflict-free) ----
    // Task map: lr = t % 42, chunk = t / 42. Consecutive lanes hit
    // consecutive rows at stride 368B (odd x16) -> conflict-free loads;
    // Hs stride 528B (odd x16) -> conflict-free stores.
    for (int t = tid; t < HTILE * (TX / 4); t += 256) {
        const int lr  = t % HTILE;
        const int cc4 = (t / HTILE) << 2;   // float2 col base (16B aligned)

        u64 axy[4] = {0ull, 0ull, 0ull, 0ull};
        u64 azw[4] = {0ull, 0ull, 0ull, 0ull};
#pragma unroll
        for (int q = 0; q < 7; q++) {
            float4 vq = *(const float4*)&xys[lr][cc4 + 2 * q];
#pragma unroll
            for (int e = 0; e < 2; e++) {
                const int j = 2 * q + e;
                float vx = e ? vq.z : vq.x;
                float vy = e ? vq.w : vq.y;
                u64 vxy = pack2(vx, vy);
                u64 vzw = pack2(fmaf(vx, vx, vy * vy), vx * vy);
#pragma unroll
                for (int i = 0; i < 4; i++) {
                    if (j >= i && j <= i + 10) {
                        FMA2(axy[i], GWP(j - i), vxy);
                        FMA2(azw[i], GWP(j - i), vzw);
                    }
                }
            }
        }
#pragma unroll
        for (int i = 0; i < 4; i++) {
            float hx, hy, hz, hw;
            unpack2(axy[i], hx, hy);
            unpack2(azw[i], hz, hw);
            Hs[lr][cc4 + i] = make_float4(hx, hy, hz, hw);
        }
    }
    __syncthreads();

    // ---- Phase 2: vertical conv + SSIM, 8-row blocking, single pass ----
    // warps 0-3: 32 cols x 4 groups x 8 rows = 1024 px, 18 LDS.128 each
    // (within-row consecutive lanes -> conflict-free).
    if (tid < 128) {
        const int lane = tid & 31;
        const int wrow = (tid >> 5) << 3;   // warp w -> output rows 8w..8w+7
        const float C1 = 0.0001f, C2 = 0.0009f;

        u64 axy[8] = {0ull,0ull,0ull,0ull,0ull,0ull,0ull,0ull};
        u64 azw[8] = {0ull,0ull,0ull,0ull,0ull,0ull,0ull,0ull};
#pragma unroll
        for (int j = 0; j < 18; j++) {
            float4 v = Hs[wrow + j][lane];
            u64 vxy = pack2(v.x, v.y);
            u64 vzw = pack2(v.z, v.w);
#pragma unroll
            for (int i = 0; i < 8; i++) {
                if (j >= i && j <= i + 10) {
                    FMA2(axy[i], GWP(j - i), vxy);
                    FMA2(azw[i], GWP(j - i), vzw);
                }
            }
        }

        float local = 0.f;
#pragma unroll
        for (int i = 0; i < 8; i++) {
            float m1, m2, czz, cxy;
            unpack2(axy[i], m1, m2);
            unpack2(azw[i], czz, cxy);
            float A = m1 * m2;
            float B = fmaf(m1, m1, m2 * m2);
            float num = (2.f * A + C1) * (2.f * (cxy - A) + C2);
            float den = (B + C1) * ((czz - B) + C2);
            local += __fdividef(num, den);
        }

        // warp reduction (warps 0-3 fully active)
#pragma unroll
        for (int o = 16; o; o >>= 1) local += __shfl_down_sync(0xffffffffu, local, o);
        if (lane == 0) red[tid >> 5] = local;
    }
    __syncthreads();

    __shared__ bool amLast;
    if (tid == 0) {
        float s = red[0] + red[1] + red[2] + red[3];
        int bidx = (blockIdx.z * GY + blockIdx.y) * GX + blockIdx.x;
        g_part[bidx] = s;
        __threadfence();
        int prev = atomicAdd(&g_count, 1);
        amLast = (prev == NBLK - 1);
    }
    __syncthreads();

    // ---- last block: deterministic final reduction (fixed-order reads) ----
    if (amLast) {
        __threadfence();
        double s = 0.0;
        for (int i = tid; i < NBLK; i += 256) s += (double)g_part[i];
#pragma unroll
        for (int o = 16; o; o >>= 1) s += __shfl_down_sync(0xffffffffu, s, o);
        __shared__ double dred[8];
        if ((tid & 31) == 0) dred[tid >> 5] = s;
        __syncthreads();
        if (tid == 0) {
            double tot = 0.0;
#pragma unroll
            for (int w = 0; w < 8; w++) tot += dred[w];
            out[0] = (float)(1.0 - tot / NPIXD);
            g_count = 0;   // reset for next graph replay
        }
    }
}

extern "C" void kernel_launch(void* const* d_in, const int* in_sizes, int n_in,
                              void* d_out, int out_size) {
    const float* pred  = (const float*)d_in[0];
    const float* label = (const float*)d_in[1];
    float* out = (float*)d_out;

    dim3 grid(GX, GY, NPLANES);   // 16 x 16 x 48
    ssim_main<<<grid, 256>>>(pred, label, out);
}

// round 16
// speedup vs baseline: 1.1803x; 1.1803x over previous
#include <cuda_runtime.h>

#define IMG     512
#define TX      32
#define TY      32
#define RAD     5
#define HTILE   (TY + 10)   /* 42 */
#define WTILE   (TX + 10)   /* 42 */
#define WPAD    46   /* float2 row stride: 368B = 112 mod 128 (odd x16) */
#define HPAD4   33   /* float4 row stride: 528B = 16 mod 128 (odd x16) */
#define GX      (IMG / TX)  /* 16 */
#define GY      (IMG / TY)  /* 16 */
#define NPLANES 48
#define NBLK    (GX * GY * NPLANES)  /* 12288 */
#define NPIXD   12582912.0

// Gaussian window (sigma=1.5, K=11), normalized.
#define G0  1.0283800e-03f
#define G1  7.5988187e-03f
#define G2  3.6000773e-02f
#define G3  1.0936069e-01f
#define G4  2.1300553e-01f
#define G5  2.6601131e-01f

typedef unsigned long long u64;

// Packed f32x2 helpers (Blackwell). One FFMA2 = two independent fp32 FMAs.
__device__ __forceinline__ u64 pack2(float lo, float hi) {
    u64 r;
    asm("mov.b64 %0, {%1, %2};" : "=l"(r) : "f"(lo), "f"(hi));
    return r;
}
__device__ __forceinline__ void unpack2(u64 v, float& lo, float& hi) {
    asm("mov.b64 {%0, %1}, %2;" : "=f"(lo), "=f"(hi) : "l"(v));
}
#define FMA2(acc, coef, v) \
    asm("fma.rn.f32x2 %0, %1, %2, %0;" : "+l"(acc) : "l"(coef), "l"(v))

// Packed coefficient pair for tap k (symmetric window), compile-time select.
#define GWP(k) ((k)==0||(k)==10 ? GP0 : (k)==1||(k)==9 ? GP1 : \
                (k)==2||(k)==8  ? GP2 : (k)==3||(k)==7 ? GP3 : \
                (k)==4||(k)==6  ? GP4 : GP5)

__device__ float g_part[NBLK];
__device__ int   g_count = 0;

__global__ __launch_bounds__(256, 5) void ssim_main(const float* __restrict__ x,
                                                    const float* __restrict__ y,
                                                    float* __restrict__ out) {
    // After horizontal conv, all 4 fields packed per point: (hx, hy, hz, hw)
    //   z = x^2 + y^2 (conv linearity),  w = x*y
    __shared__ float2 xys[HTILE][WPAD];     // (x, y) input tile   15.5 KB
    __shared__ float4 Hs[HTILE][HPAD4];     // packed H fields     22.2 KB
    __shared__ float  red[4];

    const int tid   = threadIdx.x;
    const int plane = blockIdx.z;
    const int c0    = blockIdx.x * TX;
    const int r0    = blockIdx.y * TY;
    const float* xp = x + (size_t)plane * (IMG * IMG);
    const float* yp = y + (size_t)plane * (IMG * IMG);

    // Packed (G,G) coefficient pairs — warp-uniform.
    const u64 GP0 = pack2(G0, G0);
    const u64 GP1 = pack2(G1, G1);
    const u64 GP2 = pack2(G2, G2);
    const u64 GP3 = pack2(G3, G3);
    const u64 GP4 = pack2(G4, G4);
    const u64 GP5 = pack2(G5, G5);

    // ---- Phase 0: halo load, one column per thread, 7 rows unrolled ----
    if (tid < 252) {
        const int c  = tid % WTILE;       // tile column 0..41
        const int g6 = tid / WTILE;       // row group 0..5
        const int gc = c0 + c - RAD;
        const bool okc = (gc >= 0) & (gc < IMG);
#pragma unroll
        for (int k = 0; k < 7; k++) {
            int lr = g6 * 7 + k;
            int gr = r0 + lr - RAD;
            bool ok = okc & (gr >= 0) & (gr < IMG);
            float xv = 0.f, yv = 0.f;
            if (ok) {
                int g = gr * IMG + gc;
                xv = xp[g];
                yv = yp[g];
            }
            xys[lr][c] = make_float2(xv, yv);
        }
    }
    __syncthreads();

    // ---- Phase 1: horizontal conv; lanes span ROWS (conflict-free) ----
    // Task map: lr = t % 42, chunk = t / 42. 8 consecutive lanes hit 8
    // consecutive rows at stride 368B = 112 mod 128 -> 8 distinct bank
    // slots per phase for loads; Hs stride 528B = 16 mod 128 -> distinct
    // slots for stores.
    for (int t = tid; t < HTILE * (TX / 4); t += 256) {
        const int lr  = t % HTILE;
        const int cc4 = (t / HTILE) << 2;   // float2 col base (16B aligned)

        u64 axy[4] = {0ull, 0ull, 0ull, 0ull};
        u64 azw[4] = {0ull, 0ull, 0ull, 0ull};
#pragma unroll
        for (int q = 0; q < 7; q++) {
            float4 vq = *(const float4*)&xys[lr][cc4 + 2 * q];
#pragma unroll
            for (int e = 0; e < 2; e++) {
                const int j = 2 * q + e;
                float vx = e ? vq.z : vq.x;
                float vy = e ? vq.w : vq.y;
                u64 vxy = pack2(vx, vy);
                u64 vzw = pack2(fmaf(vx, vx, vy * vy), vx * vy);
#pragma unroll
                for (int i = 0; i < 4; i++) {
                    if (j >= i && j <= i + 10) {
                        FMA2(axy[i], GWP(j - i), vxy);
                        FMA2(azw[i], GWP(j - i), vzw);
                    }
                }
            }
        }
#pragma unroll
        for (int i = 0; i < 4; i++) {
            float hx, hy, hz, hw;
            unpack2(axy[i], hx, hy);
            unpack2(azw[i], hz, hw);
            Hs[lr][cc4 + i] = make_float4(hx, hy, hz, hw);
        }
    }
    __syncthreads();

    // ---- Phase 2: vertical conv + SSIM, 8-row blocking, single pass ----
    // warps 0-3: 32 cols x 4 groups x 8 rows = 1024 px, 18 LDS.128 each
    // (within-row consecutive lanes -> conflict-free).
    if (tid < 128) {
        const int lane = tid & 31;
        const int wrow = (tid >> 5) << 3;   // warp w -> output rows 8w..8w+7
        const float C1 = 0.0001f, C2 = 0.0009f;

        u64 axy[8] = {0ull,0ull,0ull,0ull,0ull,0ull,0ull,0ull};
        u64 azw[8] = {0ull,0ull,0ull,0ull,0ull,0ull,0ull,0ull};
#pragma unroll
        for (int j = 0; j < 18; j++) {
            float4 v = Hs[wrow + j][lane];
            u64 vxy = pack2(v.x, v.y);
            u64 vzw = pack2(v.z, v.w);
#pragma unroll
            for (int i = 0; i < 8; i++) {
                if (j >= i && j <= i + 10) {
                    FMA2(axy[i], GWP(j - i), vxy);
                    FMA2(azw[i], GWP(j - i), vzw);
                }
            }
        }

        float local = 0.f;
#pragma unroll
        for (int i = 0; i < 8; i++) {
            float m1, m2, czz, cxy;
            unpack2(axy[i], m1, m2);
            unpack2(azw[i], czz, cxy);
            float A = m1 * m2;
            float B = fmaf(m1, m1, m2 * m2);
            float num = (2.f * A + C1) * (2.f * (cxy - A) + C2);
            float den = (B + C1) * ((czz - B) + C2);
            local += __fdividef(num, den);
        }

        // warp reduction (warps 0-3 fully active)
#pragma unroll
        for (int o = 16; o; o >>= 1) local += __shfl_down_sync(0xffffffffu, local, o);
        if (lane == 0) red[tid >> 5] = local;
    }
    __syncthreads();

    __shared__ bool amLast;
    if (tid == 0) {
        float s = red[0] + red[1] + red[2] + red[3];
        int bidx = (blockIdx.z * GY + blockIdx.y) * GX + blockIdx.x;
        g_part[bidx] = s;
        __threadfence();
        int prev = atomicAdd(&g_count, 1);
        amLast = (prev == NBLK - 1);
    }
    __syncthreads();

    // ---- last block: deterministic final reduction (fixed-order reads) ----
    if (amLast) {
        __threadfence();
        double s = 0.0;
        for (int i = tid; i < NBLK; i += 256) s += (double)g_part[i];
#pragma unroll
        for (int o = 16; o; o >>= 1) s += __shfl_down_sync(0xffffffffu, s, o);
        __shared__ double dred[8];
        if ((tid & 31) == 0) dred[tid >> 5] = s;
        __syncthreads();
        if (tid == 0) {
            double tot = 0.0;
#pragma unroll
            for (int w = 0; w < 8; w++) tot += dred[w];
            out[0] = (float)(1.0 - tot / NPIXD);
            g_count = 0;   // reset for next graph replay
        }
    }
}

extern "C" void kernel_launch(void* const* d_in, const int* in_sizes, int n_in,
                              void* d_out, int out_size) {
    const float* pred  = (const float*)d_in[0];
    const float* label = (const float*)d_in[1];
    float* out = (float*)d_out;

    dim3 grid(GX, GY, NPLANES);   // 16 x 16 x 48
    ssim_main<<<grid, 256>>>(pred, label, out);
}